// round 10
// baseline (speedup 1.0000x reference)
#include <cuda_runtime.h>
#include <cuda_bf16.h>
#include <cstdint>

#define BB   16
#define DD   64
#define LL   2048
#define KK   1000
#define KPAD 1024
#define NN   (BB * LL)             // 32768 tokens
#define TM2  256                   // tokens per CTA
#define KC   128                   // codes per chunk
#define NCHUNK 8
#define NBLK (NN / TM2)            // 128 CTAs
#define THREADS 512                // 16 warps

#define OUT_ELEMS (BB * DD * LL)
#define LOSS_OFF  OUT_ELEMS
#define USAGE_OFF (OUT_ELEMS + 1)
#define IDX_OFF   (OUT_ELEMS + 2)

// SMEM layout (bytes). Token/code row stride = 72 bf16 = 144 B (conflict-free)
#define ROWB     144
#define A_BLK    (TM2 * ROWB)          // 36864 per split block
#define SM_A     0                     // 3 blocks: 110592
#define B_BLK    (KC * ROWB)           // 18432 per split block
#define B_BUF    (3 * B_BLK)           // 55296 per buffer
#define SM_B     110592                // 2 buffers: 110592 -> ends 221184
#define SM_SE    221184                // float[1024]
#define SM_XN    225280                // float[512] (per-half token norms)
#define SM_TOTAL 227328
// Overlays on the B region (only used AFTER the mainloop):
#define SM_RV    SM_B                  // float[256][4]
#define SM_RI    (SM_B + 4096)         // int[256][4]
#define SM_II    (SM_B + 8192)         // int[256]
#define SM_LS    (SM_B + 9216)         // float[16]

#define CHUNK_BYTES (3 * KC * DD * 2)  // 49152 per chunk image

__device__ __align__(16) unsigned short g_esplit[NCHUNK][3 * KC * DD];
__device__ float g_enorm[KPAD];
__device__ float g_partial[NBLK];
__device__ int   g_flags[KK];
__device__ int   g_done;

// ---------------- helpers ----------------
__device__ __forceinline__ uint32_t smem_u32(const void* p) {
    uint32_t a;
    asm("{ .reg .u64 t; cvta.to.shared.u64 t, %1; cvt.u32.u64 %0, t; }"
        : "=r"(a) : "l"(p));
    return a;
}
__device__ __forceinline__ uint32_t lds32(uint32_t a) {
    uint32_t v;
    asm("ld.shared.b32 %0, [%1];" : "=r"(v) : "r"(a));
    return v;
}
__device__ __forceinline__ void sts32(uint32_t a, uint32_t v) {
    asm volatile("st.shared.b32 [%0], %1;" :: "r"(a), "r"(v) : "memory");
}
__device__ __forceinline__ void mma16816(float* c, const uint32_t* a,
                                         uint32_t b0, uint32_t b1) {
    asm volatile("mma.sync.aligned.m16n8k16.row.col.f32.bf16.bf16.f32 "
                 "{%0,%1,%2,%3}, {%4,%5,%6,%7}, {%8,%9}, {%0,%1,%2,%3};"
                 : "+f"(c[0]), "+f"(c[1]), "+f"(c[2]), "+f"(c[3])
                 : "r"(a[0]), "r"(a[1]), "r"(a[2]), "r"(a[3]),
                   "r"(b0), "r"(b1));
}
#define CP_ASYNC16(dst, src) \
    asm volatile("cp.async.cg.shared.global [%0], [%1], 16;" \
                 :: "r"(dst), "l"(src) : "memory")
#define CP_COMMIT() asm volatile("cp.async.commit_group;" ::: "memory")
#define CP_WAIT0()  asm volatile("cp.async.wait_group 0;" ::: "memory")

// ---- prep: 3-way bf16 split of codebook + fp32 norms ----
__global__ void __launch_bounds__(256, 4)
vq_prep(const float* __restrict__ emb) {
    __shared__ float hsum[8];
    int tid = threadIdx.x;
    int idx = blockIdx.x * 256 + tid;
    int k = idx >> 6, d = idx & 63;
    float e = (k < KK) ? emb[(size_t)k * DD + d] : 0.0f;

    float pn = e * e;
    #pragma unroll
    for (int off = 16; off > 0; off >>= 1)
        pn += __shfl_xor_sync(0xffffffffu, pn, off);
    if ((tid & 31) == 0) hsum[tid >> 5] = pn;

    __nv_bfloat16 b1 = __float2bfloat16(e);
    float r1 = e - __bfloat162float(b1);
    __nv_bfloat16 b2 = __float2bfloat16(r1);
    __nv_bfloat16 b3 = __float2bfloat16(r1 - __bfloat162float(b2));

    int ch = k >> 7, kc = k & 127;
    unsigned short* base = &g_esplit[ch][0];
    base[(0 * KC + kc) * DD + d] = __bfloat16_as_ushort(b1);
    base[(1 * KC + kc) * DD + d] = __bfloat16_as_ushort(b2);
    base[(2 * KC + kc) * DD + d] = __bfloat16_as_ushort(b3);

    __syncthreads();
    if (tid < 4) {
        int kk2 = blockIdx.x * 4 + tid;
        g_enorm[kk2] = (kk2 < KK) ? (hsum[2 * tid] + hsum[2 * tid + 1]) : 3.4e38f;
    }
}

// ---- main: HMMA split-GEMM + argmin + gather + loss + fused finalize ----
__global__ void __launch_bounds__(THREADS, 1)
vq_main(const float* __restrict__ x, const float* __restrict__ emb,
        float* __restrict__ dout) {
    extern __shared__ char smem[];
    const uint32_t sb = smem_u32(smem);
    float* se  = (float*)(smem + SM_SE);
    float* xns = (float*)(smem + SM_XN);
    float* rv2 = (float*)(smem + SM_RV);
    int*   ri2 = (int*)(smem + SM_RI);
    int*   ii  = (int*)(smem + SM_II);
    float* ls  = (float*)(smem + SM_LS);
    __shared__ int amlast;
    __shared__ int cnt_s;

    const int tid  = threadIdx.x;
    const int warp = tid >> 5;
    const int lane = tid & 31;
    const int wm   = warp & 3;     // m-slice (64 tokens)
    const int wn   = warp >> 2;    // n-slice (32 codes)
    const int lq   = lane >> 2;    // 0..7
    const int lr   = lane & 3;     // 0..3
    const int b    = blockIdx.x >> 3;
    const int l0   = (blockIdx.x & 7) * TM2;

    // Start B chunk-0 copy early
    {
        const char* src = (const char*)&g_esplit[0][0];
        uint32_t dstb = sb + SM_B;
        for (int i = tid; i < CHUNK_BYTES / 16; i += THREADS) {
            int row = i >> 3, q = i & 7;
            CP_ASYNC16(dstb + row * ROWB + q * 16, src + row * 128 + q * 16);
        }
        CP_COMMIT();
    }

    // A build: thread owns (token t, d-half): 32 dims each
    {
        const int t    = tid & 255;
        const int half = tid >> 8;
        const int d0   = half * 32;
        const float* xp = x + (size_t)b * DD * LL + (size_t)d0 * LL + l0 + t;
        float xn = 0.0f;
        #pragma unroll
        for (int dd = 0; dd < 32; dd += 2) {
            float v0 = xp[(size_t)dd * LL];
            float v1 = xp[(size_t)(dd + 1) * LL];
            xn += v0 * v0 + v1 * v1;
            __nv_bfloat16 a1 = __float2bfloat16(v0);
            float r = v0 - __bfloat162float(a1);
            __nv_bfloat16 a2 = __float2bfloat16(r);
            __nv_bfloat16 a3 = __float2bfloat16(r - __bfloat162float(a2));
            __nv_bfloat16 c1 = __float2bfloat16(v1);
            float q = v1 - __bfloat162float(c1);
            __nv_bfloat16 c2 = __float2bfloat16(q);
            __nv_bfloat16 c3 = __float2bfloat16(q - __bfloat162float(c2));
            uint32_t base = sb + SM_A + t * ROWB + (d0 + dd) * 2;
            sts32(base,             (uint32_t)__bfloat16_as_ushort(a1) |
                                    ((uint32_t)__bfloat16_as_ushort(c1) << 16));
            sts32(base + A_BLK,     (uint32_t)__bfloat16_as_ushort(a2) |
                                    ((uint32_t)__bfloat16_as_ushort(c2) << 16));
            sts32(base + 2 * A_BLK, (uint32_t)__bfloat16_as_ushort(a3) |
                                    ((uint32_t)__bfloat16_as_ushort(c3) << 16));
        }
        xns[tid] = xn;   // per-half partial; token norm = xns[t] + xns[t+256]
    }
    for (int i = tid; i < KPAD; i += THREADS) se[i] = g_enorm[i];

    CP_WAIT0();
    __syncthreads();

    float bestv[8];
    int   besti[8];
    #pragma unroll
    for (int s = 0; s < 8; s++) { bestv[s] = 3.0e38f; besti[s] = 0; }

    const uint32_t aW = sb + SM_A + wm * 64 * ROWB + lq * ROWB + lr * 4;
    const uint32_t bW = sb + SM_B + wn * 32 * ROWB + lq * ROWB + lr * 4;

    for (int c = 0; c < NCHUNK; c++) {
        const int buf = c & 1;
        if (c + 1 < NCHUNK) {
            const char* src = (const char*)&g_esplit[c + 1][0];
            uint32_t dstb = sb + SM_B + ((c + 1) & 1) * B_BUF;
            for (int i = tid; i < CHUNK_BYTES / 16; i += THREADS) {
                int row = i >> 3, q = i & 7;
                CP_ASYNC16(dstb + row * ROWB + q * 16, src + row * 128 + q * 16);
            }
            CP_COMMIT();
        }

        float acc[4][4][4];
        #pragma unroll
        for (int mt = 0; mt < 4; mt++)
            #pragma unroll
            for (int nt = 0; nt < 4; nt++)
                #pragma unroll
                for (int r = 0; r < 4; r++) acc[mt][nt][r] = 0.0f;

        // Products grouped by B split: pb=0 x {x1,x2,x3}, pb=1 x {x1,x2}, pb=2 x {x1}
        #pragma unroll
        for (int pb = 0; pb < 3; pb++) {
            const int npa = (pb == 0) ? 3 : ((pb == 1) ? 2 : 1);
            const uint32_t bb = bW + buf * B_BUF + pb * B_BLK;
            #pragma unroll
            for (int ks = 0; ks < 4; ks++) {
                const uint32_t ko = (uint32_t)ks * 32;
                uint32_t bf[4][2];
                #pragma unroll
                for (int nt = 0; nt < 4; nt++) {
                    uint32_t bbase = bb + nt * 8 * ROWB + ko;
                    bf[nt][0] = lds32(bbase);
                    bf[nt][1] = lds32(bbase + 16);
                }
                #pragma unroll
                for (int pa = 0; pa < 3; pa++) {
                    if (pa >= npa) break;
                    uint32_t ab = aW + pa * A_BLK;
                    uint32_t a[4][4];
                    #pragma unroll
                    for (int mt = 0; mt < 4; mt++) {
                        uint32_t base = ab + mt * 16 * ROWB + ko;
                        a[mt][0] = lds32(base);
                        a[mt][1] = lds32(base + 8 * ROWB);
                        a[mt][2] = lds32(base + 16);
                        a[mt][3] = lds32(base + 8 * ROWB + 16);
                    }
                    #pragma unroll
                    for (int nt = 0; nt < 4; nt++)
                        #pragma unroll
                        for (int mt = 0; mt < 4; mt++)
                            mma16816(acc[mt][nt], a[mt], bf[nt][0], bf[nt][1]);
                }
            }
        }

        // Argmin on this chunk's distances
        #pragma unroll
        for (int nt = 0; nt < 4; nt++) {
            int cbase = c * KC + wn * 32 + nt * 8 + lr * 2;
            float2 en = *(const float2*)(se + cbase);
            #pragma unroll
            for (int mt = 0; mt < 4; mt++) {
                #pragma unroll
                for (int h = 0; h < 2; h++) {
                    int s = mt * 2 + h;
                    float m0 = fmaf(-2.0f, acc[mt][nt][2 * h],     en.x);
                    float m1 = fmaf(-2.0f, acc[mt][nt][2 * h + 1], en.y);
                    if (m0 < bestv[s] || (m0 == bestv[s] && cbase < besti[s]))
                        { bestv[s] = m0; besti[s] = cbase; }
                    if (m1 < bestv[s] || (m1 == bestv[s] && cbase + 1 < besti[s]))
                        { bestv[s] = m1; besti[s] = cbase + 1; }
                }
            }
        }

        CP_WAIT0();
        __syncthreads();
    }

    // Reduce across the 4 lanes (lr) sharing each token row
    #pragma unroll
    for (int s = 0; s < 8; s++) {
        #pragma unroll
        for (int off = 1; off <= 2; off <<= 1) {
            float ov = __shfl_xor_sync(0xffffffffu, bestv[s], off);
            int   oi = __shfl_xor_sync(0xffffffffu, besti[s], off);
            if (ov < bestv[s] || (ov == bestv[s] && oi < besti[s]))
                { bestv[s] = ov; besti[s] = oi; }
        }
    }
    if (lr == 0) {
        #pragma unroll
        for (int mt = 0; mt < 4; mt++)
            #pragma unroll
            for (int h = 0; h < 2; h++) {
                int t = wm * 64 + mt * 16 + lq + 8 * h;
                rv2[t * 4 + wn] = bestv[mt * 2 + h];
                ri2[t * 4 + wn] = besti[mt * 2 + h];
            }
    }
    __syncthreads();

    // Final per-token merge of the 4 n-groups + outputs (threads 0..255)
    if (tid < 256) {
        float bv = rv2[tid * 4];
        int   bi = ri2[tid * 4];
        #pragma unroll
        for (int g = 1; g < 4; g++) {
            float v  = rv2[tid * 4 + g];
            int   ix = ri2[tid * 4 + g];
            if (v < bv || (v == bv && ix < bi)) { bv = v; bi = ix; }
        }
        dout[IDX_OFF + b * LL + l0 + tid] = (float)bi;
        ii[tid] = bi;
        g_flags[bi] = 1;
        float sd = xns[tid] + xns[tid + 256] + bv;
        #pragma unroll
        for (int off = 16; off > 0; off >>= 1)
            sd += __shfl_down_sync(0xffffffffu, sd, off);
        if (lane == 0) ls[warp] = sd;
    }
    __syncthreads();
    if (tid == 0) {
        float s = 0.0f;
        #pragma unroll
        for (int w = 0; w < 8; w++) s += ls[w];
        g_partial[blockIdx.x] = s;
    }

    // Gather + transpose write (coalesced stores)
    for (int i = tid; i < DD * TM2; i += THREADS) {
        int d = i >> 8, t = i & 255;
        dout[((size_t)(b * DD + d)) * LL + l0 + t] = emb[(size_t)ii[t] * DD + d];
    }

    // ---- fused finalize: last CTA reduces loss + usage, resets state ----
    __threadfence();
    if (tid == 0) {
        int old = atomicAdd(&g_done, 1);
        amlast = (old == NBLK - 1) ? 1 : 0;
        cnt_s = 0;
    }
    __syncthreads();
    if (amlast) {
        __threadfence();
        float s = (tid < NBLK) ? g_partial[tid] : 0.0f;
        #pragma unroll
        for (int off = 16; off > 0; off >>= 1)
            s += __shfl_down_sync(0xffffffffu, s, off);
        if (lane == 0) ls[warp] = s;

        int f = 0;
        for (int i = tid; i < KK; i += THREADS) {
            f += g_flags[i];
            g_flags[i] = 0;
        }
        #pragma unroll
        for (int off = 16; off > 0; off >>= 1)
            f += __shfl_down_sync(0xffffffffu, f, off);
        if (lane == 0) atomicAdd(&cnt_s, f);
        __syncthreads();
        if (tid == 0) {
            float lsum = 0.0f;
            #pragma unroll
            for (int w = 0; w < 16; w++) lsum += ls[w];
            dout[LOSS_OFF]  = 11.0f * lsum / (float)(NN * DD);
            dout[USAGE_OFF] = (float)cnt_s;
            g_done = 0;
            __threadfence();
        }
    }
}

extern "C" void kernel_launch(void* const* d_in, const int* in_sizes, int n_in,
                              void* d_out, int out_size) {
    (void)n_in; (void)out_size;
    const float* x;
    const float* emb;
    if (in_sizes[0] == KK * DD) { emb = (const float*)d_in[0]; x = (const float*)d_in[1]; }
    else                        { x   = (const float*)d_in[0]; emb = (const float*)d_in[1]; }
    float* out = (float*)d_out;

    cudaFuncSetAttribute(vq_main, cudaFuncAttributeMaxDynamicSharedMemorySize,
                         SM_TOTAL);

    vq_prep<<<KPAD / 4, 256>>>(emb);
    vq_main<<<NBLK, THREADS, SM_TOTAL>>>(x, emb, out);
}

// round 11
// speedup vs baseline: 1.3673x; 1.3673x over previous
#include <cuda_runtime.h>
#include <cuda_bf16.h>
#include <cstdint>

#define BB   16
#define DD   64
#define LL   2048
#define KK   1000
#define KPAD 1024
#define NN   (BB * LL)             // 32768 tokens
#define TM2  256                   // tokens per CTA
#define KC   128                   // codes per chunk
#define NCHUNK 8
#define NBLK (NN / TM2)            // 128 CTAs
#define THREADS 256                // 8 warps (255-reg envelope)

#define OUT_ELEMS (BB * DD * LL)
#define LOSS_OFF  OUT_ELEMS
#define USAGE_OFF (OUT_ELEMS + 1)
#define IDX_OFF   (OUT_ELEMS + 2)

// SMEM layout (bytes). Token/code row stride = 72 bf16 = 144 B (conflict-free)
#define ROWB     144
#define A_BLK    (TM2 * ROWB)          // 36864 per split block
#define SM_A     0                     // 3 blocks: 110592
#define B_BLK    (KC * ROWB)           // 18432 per split block
#define B_BUF    (3 * B_BLK)           // 55296 per buffer
#define SM_B     110592                // 2 buffers: 110592
#define SM_SE    221184                // float[1024] code norms
#define SM_XN    225280                // float[256] token norms
#define SM_RV    226304                // float[256][2]
#define SM_RI    228352                // int[256][2]
#define SM_II    230400                // int[256]
#define SM_LS    231424                // float[8]
#define SM_TOTAL 231488

#define CHUNK_BYTES (3 * KC * DD * 2)  // 49152 per chunk image

__device__ __align__(16) unsigned short g_esplit[NCHUNK][3 * KC * DD];
__device__ float g_enorm[KPAD];
__device__ float g_partial[NBLK];
__device__ int   g_flags[KK];
__device__ int   g_done;

// ---------------- helpers ----------------
__device__ __forceinline__ uint32_t smem_u32(const void* p) {
    uint32_t a;
    asm("{ .reg .u64 t; cvta.to.shared.u64 t, %1; cvt.u32.u64 %0, t; }"
        : "=r"(a) : "l"(p));
    return a;
}
__device__ __forceinline__ void sts32(uint32_t a, uint32_t v) {
    asm volatile("st.shared.b32 [%0], %1;" :: "r"(a), "r"(v) : "memory");
}
__device__ __forceinline__ void ldmx4(uint32_t& r0, uint32_t& r1,
                                      uint32_t& r2, uint32_t& r3, uint32_t a) {
    asm volatile("ldmatrix.sync.aligned.m8n8.x4.shared.b16 {%0,%1,%2,%3}, [%4];"
                 : "=r"(r0), "=r"(r1), "=r"(r2), "=r"(r3) : "r"(a));
}
__device__ __forceinline__ void mma16816(float* c, const uint32_t* a,
                                         uint32_t b0, uint32_t b1) {
    asm volatile("mma.sync.aligned.m16n8k16.row.col.f32.bf16.bf16.f32 "
                 "{%0,%1,%2,%3}, {%4,%5,%6,%7}, {%8,%9}, {%0,%1,%2,%3};"
                 : "+f"(c[0]), "+f"(c[1]), "+f"(c[2]), "+f"(c[3])
                 : "r"(a[0]), "r"(a[1]), "r"(a[2]), "r"(a[3]),
                   "r"(b0), "r"(b1));
}
#define CP_ASYNC16(dst, src) \
    asm volatile("cp.async.cg.shared.global [%0], [%1], 16;" \
                 :: "r"(dst), "l"(src) : "memory")
#define CP_COMMIT() asm volatile("cp.async.commit_group;" ::: "memory")
#define CP_WAIT0()  asm volatile("cp.async.wait_group 0;" ::: "memory")

// ---- prep: 3-way bf16 split of codebook + fp32 norms ----
__global__ void __launch_bounds__(256, 4)
vq_prep(const float* __restrict__ emb) {
    __shared__ float hsum[8];
    int tid = threadIdx.x;
    int idx = blockIdx.x * 256 + tid;
    int k = idx >> 6, d = idx & 63;
    float e = (k < KK) ? emb[(size_t)k * DD + d] : 0.0f;

    float pn = e * e;
    #pragma unroll
    for (int off = 16; off > 0; off >>= 1)
        pn += __shfl_xor_sync(0xffffffffu, pn, off);
    if ((tid & 31) == 0) hsum[tid >> 5] = pn;

    __nv_bfloat16 b1 = __float2bfloat16(e);
    float r1 = e - __bfloat162float(b1);
    __nv_bfloat16 b2 = __float2bfloat16(r1);
    __nv_bfloat16 b3 = __float2bfloat16(r1 - __bfloat162float(b2));

    int ch = k >> 7, kc = k & 127;
    unsigned short* base = &g_esplit[ch][0];
    base[(0 * KC + kc) * DD + d] = __bfloat16_as_ushort(b1);
    base[(1 * KC + kc) * DD + d] = __bfloat16_as_ushort(b2);
    base[(2 * KC + kc) * DD + d] = __bfloat16_as_ushort(b3);

    __syncthreads();
    if (tid < 4) {
        int kk2 = blockIdx.x * 4 + tid;
        g_enorm[kk2] = (kk2 < KK) ? (hsum[2 * tid] + hsum[2 * tid + 1]) : 3.4e38f;
    }
}

// ---- main: HMMA split-GEMM + argmin + gather + loss + fused finalize ----
__global__ void __launch_bounds__(THREADS, 1)
vq_main(const float* __restrict__ x, const float* __restrict__ emb,
        float* __restrict__ dout) {
    extern __shared__ char smem[];
    const uint32_t sb = smem_u32(smem);
    float* se  = (float*)(smem + SM_SE);
    float* xns = (float*)(smem + SM_XN);
    float* rv2 = (float*)(smem + SM_RV);
    int*   ri2 = (int*)(smem + SM_RI);
    int*   ii  = (int*)(smem + SM_II);
    float* ls  = (float*)(smem + SM_LS);
    __shared__ int amlast;
    __shared__ int cnt_s;

    const int tid  = threadIdx.x;
    const int warp = tid >> 5;
    const int lane = tid & 31;
    const int wm   = warp & 3;     // m-slice (64 tokens)
    const int wn   = warp >> 2;    // n-slice (64 codes)
    const int lq   = lane >> 2;    // 0..7
    const int lr   = lane & 3;     // 0..3
    const int b    = blockIdx.x >> 3;
    const int l0   = (blockIdx.x & 7) * TM2;

    // ldmatrix per-lane offsets (within a 16-row slab at k-offset):
    // A x4: lanes 0..15 -> rows 0..15 k0, lanes 16..31 -> rows 0..15 k8(+16B)
    const uint32_t aoff = (uint32_t)(lane & 15) * ROWB + (uint32_t)(lane >> 4) * 16;
    // B x4: lanes 0..7 nt0 k0, 8..15 nt0 k8, 16..23 nt1 k0, 24..31 nt1 k8
    const uint32_t boff = (uint32_t)(lane & 7) * ROWB
                        + (uint32_t)((lane >> 3) & 1) * 16
                        + (uint32_t)(lane >> 4) * (8 * ROWB);

    // Start B chunk-0 copy early (cp.async, overlaps A build)
    {
        const char* src = (const char*)&g_esplit[0][0];
        uint32_t dstb = sb + SM_B;
        for (int i = tid; i < CHUNK_BYTES / 16; i += THREADS) {
            int row = i >> 3, q = i & 7;
            CP_ASYNC16(dstb + row * ROWB + q * 16, src + row * 128 + q * 16);
        }
        CP_COMMIT();
    }

    // A build: thread owns token t = tid
    {
        const float* xp = x + (size_t)b * DD * LL + l0 + tid;
        float xn = 0.0f;
        #pragma unroll 4
        for (int d = 0; d < DD; d += 2) {
            float v0 = xp[(size_t)d * LL];
            float v1 = xp[(size_t)(d + 1) * LL];
            xn += v0 * v0 + v1 * v1;
            __nv_bfloat16 a1 = __float2bfloat16(v0);
            float r = v0 - __bfloat162float(a1);
            __nv_bfloat16 a2 = __float2bfloat16(r);
            __nv_bfloat16 a3 = __float2bfloat16(r - __bfloat162float(a2));
            __nv_bfloat16 c1 = __float2bfloat16(v1);
            float q = v1 - __bfloat162float(c1);
            __nv_bfloat16 c2 = __float2bfloat16(q);
            __nv_bfloat16 c3 = __float2bfloat16(q - __bfloat162float(c2));
            uint32_t base = sb + SM_A + tid * ROWB + d * 2;
            sts32(base,             (uint32_t)__bfloat16_as_ushort(a1) |
                                    ((uint32_t)__bfloat16_as_ushort(c1) << 16));
            sts32(base + A_BLK,     (uint32_t)__bfloat16_as_ushort(a2) |
                                    ((uint32_t)__bfloat16_as_ushort(c2) << 16));
            sts32(base + 2 * A_BLK, (uint32_t)__bfloat16_as_ushort(a3) |
                                    ((uint32_t)__bfloat16_as_ushort(c3) << 16));
        }
        xns[tid] = xn;
    }
    for (int i = tid; i < KPAD; i += THREADS) se[i] = g_enorm[i];

    CP_WAIT0();
    __syncthreads();

    float bestv[8];
    int   besti[8];
    #pragma unroll
    for (int s = 0; s < 8; s++) { bestv[s] = 3.0e38f; besti[s] = 0; }

    const uint32_t aW = sb + SM_A + wm * 64 * ROWB + aoff;
    const uint32_t bW = sb + SM_B + wn * 64 * ROWB + boff;

    for (int c = 0; c < NCHUNK; c++) {
        const int buf = c & 1;
        if (c + 1 < NCHUNK) {
            const char* src = (const char*)&g_esplit[c + 1][0];
            uint32_t dstb = sb + SM_B + ((c + 1) & 1) * B_BUF;
            for (int i = tid; i < CHUNK_BYTES / 16; i += THREADS) {
                int row = i >> 3, q = i & 7;
                CP_ASYNC16(dstb + row * ROWB + q * 16, src + row * 128 + q * 16);
            }
            CP_COMMIT();
        }

        float acc[4][8][4];
        #pragma unroll
        for (int mt = 0; mt < 4; mt++)
            #pragma unroll
            for (int nt = 0; nt < 8; nt++)
                #pragma unroll
                for (int r = 0; r < 4; r++) acc[mt][nt][r] = 0.0f;

        // 6 split products, 4 k-steps; fragments via ldmatrix.x4
        #pragma unroll
        for (int p = 0; p < 6; p++) {
            const int pa = (p < 3) ? p : ((p < 5) ? p - 3 : 0);
            const int pb = (p < 3) ? 0 : ((p < 5) ? 1 : 2);
            const uint32_t ab = aW + pa * A_BLK;
            const uint32_t bb = bW + buf * B_BUF + pb * B_BLK;
            #pragma unroll
            for (int ks = 0; ks < 4; ks++) {
                const uint32_t ko = (uint32_t)ks * 32;
                uint32_t a[4][4];
                #pragma unroll
                for (int mt = 0; mt < 4; mt++)
                    ldmx4(a[mt][0], a[mt][1], a[mt][2], a[mt][3],
                          ab + mt * 16 * ROWB + ko);
                uint32_t bf[8][2];
                #pragma unroll
                for (int np = 0; np < 4; np++)
                    ldmx4(bf[2 * np][0], bf[2 * np][1],
                          bf[2 * np + 1][0], bf[2 * np + 1][1],
                          bb + np * 16 * ROWB + ko);
                #pragma unroll
                for (int nt = 0; nt < 8; nt++)
                    #pragma unroll
                    for (int mt = 0; mt < 4; mt++)
                        mma16816(acc[mt][nt], a[mt], bf[nt][0], bf[nt][1]);
            }
        }

        // Argmin on this chunk's distances
        #pragma unroll
        for (int nt = 0; nt < 8; nt++) {
            int cbase = c * KC + wn * 64 + nt * 8 + lr * 2;
            float2 en = *(const float2*)(se + cbase);
            #pragma unroll
            for (int mt = 0; mt < 4; mt++) {
                #pragma unroll
                for (int h = 0; h < 2; h++) {
                    int s = mt * 2 + h;
                    float m0 = fmaf(-2.0f, acc[mt][nt][2 * h],     en.x);
                    float m1 = fmaf(-2.0f, acc[mt][nt][2 * h + 1], en.y);
                    if (m0 < bestv[s] || (m0 == bestv[s] && cbase < besti[s]))
                        { bestv[s] = m0; besti[s] = cbase; }
                    if (m1 < bestv[s] || (m1 == bestv[s] && cbase + 1 < besti[s]))
                        { bestv[s] = m1; besti[s] = cbase + 1; }
                }
            }
        }

        CP_WAIT0();
        __syncthreads();
    }

    // Reduce across the 4 lanes (lr) sharing each token row
    #pragma unroll
    for (int s = 0; s < 8; s++) {
        #pragma unroll
        for (int off = 1; off <= 2; off <<= 1) {
            float ov = __shfl_xor_sync(0xffffffffu, bestv[s], off);
            int   oi = __shfl_xor_sync(0xffffffffu, besti[s], off);
            if (ov < bestv[s] || (ov == bestv[s] && oi < besti[s]))
                { bestv[s] = ov; besti[s] = oi; }
        }
    }
    if (lr == 0) {
        #pragma unroll
        for (int mt = 0; mt < 4; mt++)
            #pragma unroll
            for (int h = 0; h < 2; h++) {
                int t = wm * 64 + mt * 16 + lq + 8 * h;
                rv2[t * 2 + wn] = bestv[mt * 2 + h];
                ri2[t * 2 + wn] = besti[mt * 2 + h];
            }
    }
    __syncthreads();

    // Final per-token merge + outputs
    {
        float bv = rv2[tid * 2];
        int   bi = ri2[tid * 2];
        float v  = rv2[tid * 2 + 1];
        int   ix = ri2[tid * 2 + 1];
        if (v < bv || (v == bv && ix < bi)) { bv = v; bi = ix; }
        dout[IDX_OFF + b * LL + l0 + tid] = (float)bi;
        ii[tid] = bi;
        g_flags[bi] = 1;
        float sd = xns[tid] + bv;
        #pragma unroll
        for (int off = 16; off > 0; off >>= 1)
            sd += __shfl_down_sync(0xffffffffu, sd, off);
        if (lane == 0) ls[warp] = sd;
    }
    __syncthreads();
    if (tid == 0) {
        float s = 0.0f;
        #pragma unroll
        for (int w = 0; w < 8; w++) s += ls[w];
        g_partial[blockIdx.x] = s;
    }

    // Gather + transpose write (coalesced stores)
    for (int i = tid; i < DD * TM2; i += THREADS) {
        int d = i >> 8, t = i & 255;
        dout[((size_t)(b * DD + d)) * LL + l0 + t] = emb[(size_t)ii[t] * DD + d];
    }

    // ---- fused finalize: last CTA reduces loss + usage, resets state ----
    __threadfence();
    if (tid == 0) {
        int old = atomicAdd(&g_done, 1);
        amlast = (old == NBLK - 1) ? 1 : 0;
        cnt_s = 0;
    }
    __syncthreads();
    if (amlast) {
        __threadfence();
        float s = (tid < NBLK) ? g_partial[tid] : 0.0f;
        #pragma unroll
        for (int off = 16; off > 0; off >>= 1)
            s += __shfl_down_sync(0xffffffffu, s, off);
        if (lane == 0) ls[warp] = s;

        int f = 0;
        for (int i = tid; i < KK; i += THREADS) {
            f += g_flags[i];
            g_flags[i] = 0;
        }
        #pragma unroll
        for (int off = 16; off > 0; off >>= 1)
            f += __shfl_down_sync(0xffffffffu, f, off);
        if (lane == 0) atomicAdd(&cnt_s, f);
        __syncthreads();
        if (tid == 0) {
            float lsum = 0.0f;
            #pragma unroll
            for (int w = 0; w < 8; w++) lsum += ls[w];
            dout[LOSS_OFF]  = 11.0f * lsum / (float)(NN * DD);
            dout[USAGE_OFF] = (float)cnt_s;
            g_done = 0;
            __threadfence();
        }
    }
}

extern "C" void kernel_launch(void* const* d_in, const int* in_sizes, int n_in,
                              void* d_out, int out_size) {
    (void)n_in; (void)out_size;
    const float* x;
    const float* emb;
    if (in_sizes[0] == KK * DD) { emb = (const float*)d_in[0]; x = (const float*)d_in[1]; }
    else                        { x   = (const float*)d_in[0]; emb = (const float*)d_in[1]; }
    float* out = (float*)d_out;

    cudaFuncSetAttribute(vq_main, cudaFuncAttributeMaxDynamicSharedMemorySize,
                         SM_TOTAL);

    vq_prep<<<KPAD / 4, 256>>>(emb);
    vq_main<<<NBLK, THREADS, SM_TOTAL>>>(x, emb, out);
}

// round 12
// speedup vs baseline: 1.5139x; 1.1072x over previous
#include <cuda_runtime.h>
#include <cuda_bf16.h>
#include <cstdint>

#define BB   16
#define DD   64
#define LL   2048
#define KK   1000
#define KPAD 1024
#define NN   (BB * LL)             // 32768 tokens
#define TM2  256                   // tokens per CTA
#define KC   128                   // codes per chunk
#define NCHUNK 8
#define NBLK (NN / TM2)            // 128 CTAs
#define THREADS 256

#define OUT_ELEMS (BB * DD * LL)
#define LOSS_OFF  OUT_ELEMS
#define USAGE_OFF (OUT_ELEMS + 1)
#define IDX_OFF   (OUT_ELEMS + 2)

// SMEM layout (bytes). Token/code row stride = 72 bf16 = 144 B
#define ROWB     144
#define A_BLK    (TM2 * ROWB)          // 36864 per split block
#define SM_A     0                     // 3 blocks: 110592
#define B_BLK    (KC * ROWB)           // 18432 per split block
#define B_BUF    (3 * B_BLK)           // 55296 per buffer
#define SM_B     110592                // 2 buffers: 110592
#define SM_SE    221184                // float[1024] code norms
#define SM_XN    225280                // float[256] token norms
#define SM_RV    226304                // float[256][2]
#define SM_RI    228352                // int[256][2]
#define SM_II    230400                // int[256]
#define SM_LS    231424                // float[8]
#define SM_TOTAL 231488

#define CHUNK_BYTES (3 * KC * DD * 2)  // 49152 per chunk image

__device__ __align__(16) unsigned short g_esplit[NCHUNK][3 * KC * DD];
__device__ float g_enorm[KPAD];
__device__ float g_partial[NBLK];
__device__ int   g_flags[KK];
__device__ int   g_done;

// ---------------- helpers ----------------
__device__ __forceinline__ uint32_t smem_u32(const void* p) {
    uint32_t a;
    asm("{ .reg .u64 t; cvta.to.shared.u64 t, %1; cvt.u32.u64 %0, t; }"
        : "=r"(a) : "l"(p));
    return a;
}
__device__ __forceinline__ uint32_t lds32(uint32_t a) {
    uint32_t v;
    asm("ld.shared.b32 %0, [%1];" : "=r"(v) : "r"(a));
    return v;
}
__device__ __forceinline__ void sts32(uint32_t a, uint32_t v) {
    asm volatile("st.shared.b32 [%0], %1;" :: "r"(a), "r"(v) : "memory");
}
__device__ __forceinline__ void mma16816(float* c, const uint32_t* a,
                                         uint32_t b0, uint32_t b1) {
    asm volatile("mma.sync.aligned.m16n8k16.row.col.f32.bf16.bf16.f32 "
                 "{%0,%1,%2,%3}, {%4,%5,%6,%7}, {%8,%9}, {%0,%1,%2,%3};"
                 : "+f"(c[0]), "+f"(c[1]), "+f"(c[2]), "+f"(c[3])
                 : "r"(a[0]), "r"(a[1]), "r"(a[2]), "r"(a[3]),
                   "r"(b0), "r"(b1));
}
#define CP_ASYNC16(dst, src) \
    asm volatile("cp.async.cg.shared.global [%0], [%1], 16;" \
                 :: "r"(dst), "l"(src) : "memory")
#define CP_COMMIT() asm volatile("cp.async.commit_group;" ::: "memory")
#define CP_WAIT0()  asm volatile("cp.async.wait_group 0;" ::: "memory")

// ---- prep: 3-way bf16 split of codebook + fp32 norms ----
__global__ void __launch_bounds__(256, 4)
vq_prep(const float* __restrict__ emb) {
    __shared__ float hsum[8];
    int tid = threadIdx.x;
    int idx = blockIdx.x * 256 + tid;
    int k = idx >> 6, d = idx & 63;
    float e = (k < KK) ? emb[(size_t)k * DD + d] : 0.0f;

    float pn = e * e;
    #pragma unroll
    for (int off = 16; off > 0; off >>= 1)
        pn += __shfl_xor_sync(0xffffffffu, pn, off);
    if ((tid & 31) == 0) hsum[tid >> 5] = pn;

    __nv_bfloat16 b1 = __float2bfloat16(e);
    float r1 = e - __bfloat162float(b1);
    __nv_bfloat16 b2 = __float2bfloat16(r1);
    __nv_bfloat16 b3 = __float2bfloat16(r1 - __bfloat162float(b2));

    int ch = k >> 7, kc = k & 127;
    unsigned short* base = &g_esplit[ch][0];
    base[(0 * KC + kc) * DD + d] = __bfloat16_as_ushort(b1);
    base[(1 * KC + kc) * DD + d] = __bfloat16_as_ushort(b2);
    base[(2 * KC + kc) * DD + d] = __bfloat16_as_ushort(b3);

    __syncthreads();
    if (tid < 4) {
        int kk2 = blockIdx.x * 4 + tid;
        g_enorm[kk2] = (kk2 < KK) ? (hsum[2 * tid] + hsum[2 * tid + 1]) : 3.4e38f;
    }
}

// ---- main: HMMA split-GEMM + argmin + gather + loss + fused finalize ----
__global__ void __launch_bounds__(THREADS, 1)
vq_main(const float* __restrict__ x, const float* __restrict__ emb,
        float* __restrict__ dout) {
    extern __shared__ char smem[];
    const uint32_t sb = smem_u32(smem);
    float* se  = (float*)(smem + SM_SE);
    float* xns = (float*)(smem + SM_XN);
    float* rv2 = (float*)(smem + SM_RV);
    int*   ri2 = (int*)(smem + SM_RI);
    int*   ii  = (int*)(smem + SM_II);
    float* ls  = (float*)(smem + SM_LS);
    __shared__ int amlast;
    __shared__ int cnt_s;

    const int tid  = threadIdx.x;
    const int warp = tid >> 5;
    const int lane = tid & 31;
    const int wm   = warp & 3;     // m-slice (64 tokens)
    const int wn   = warp >> 2;    // n-slice (64 codes)
    const int lq   = lane >> 2;    // 0..7
    const int lr   = lane & 3;     // 0..3
    const int b    = blockIdx.x >> 3;
    const int l0   = (blockIdx.x & 7) * TM2;

    // Start B chunk-0 copy early (cp.async, overlaps A build)
    {
        const char* src = (const char*)&g_esplit[0][0];
        uint32_t dstb = sb + SM_B;
        for (int i = tid; i < CHUNK_BYTES / 16; i += THREADS) {
            int row = i >> 3, q = i & 7;
            CP_ASYNC16(dstb + row * ROWB + q * 16, src + row * 128 + q * 16);
        }
        CP_COMMIT();
    }

    // A build: thread owns token t = tid
    {
        const float* xp = x + (size_t)b * DD * LL + l0 + tid;
        float xn = 0.0f;
        #pragma unroll 4
        for (int d = 0; d < DD; d += 2) {
            float v0 = xp[(size_t)d * LL];
            float v1 = xp[(size_t)(d + 1) * LL];
            xn += v0 * v0 + v1 * v1;
            __nv_bfloat16 a1 = __float2bfloat16(v0);
            float r = v0 - __bfloat162float(a1);
            __nv_bfloat16 a2 = __float2bfloat16(r);
            __nv_bfloat16 a3 = __float2bfloat16(r - __bfloat162float(a2));
            __nv_bfloat16 c1 = __float2bfloat16(v1);
            float q = v1 - __bfloat162float(c1);
            __nv_bfloat16 c2 = __float2bfloat16(q);
            __nv_bfloat16 c3 = __float2bfloat16(q - __bfloat162float(c2));
            uint32_t base = sb + SM_A + tid * ROWB + d * 2;
            sts32(base,             (uint32_t)__bfloat16_as_ushort(a1) |
                                    ((uint32_t)__bfloat16_as_ushort(c1) << 16));
            sts32(base + A_BLK,     (uint32_t)__bfloat16_as_ushort(a2) |
                                    ((uint32_t)__bfloat16_as_ushort(c2) << 16));
            sts32(base + 2 * A_BLK, (uint32_t)__bfloat16_as_ushort(a3) |
                                    ((uint32_t)__bfloat16_as_ushort(c3) << 16));
        }
        xns[tid] = xn;
    }
    for (int i = tid; i < KPAD; i += THREADS) se[i] = g_enorm[i];

    CP_WAIT0();
    __syncthreads();

    float bestv[8];
    int   besti[8];
    #pragma unroll
    for (int s = 0; s < 8; s++) { bestv[s] = 3.0e38f; besti[s] = 0; }

    const uint32_t aW = sb + SM_A + wm * 64 * ROWB + lq * ROWB + lr * 4;
    const uint32_t bW = sb + SM_B + wn * 64 * ROWB + lq * ROWB + lr * 4;

    for (int c = 0; c < NCHUNK; c++) {
        const int buf = c & 1;
        if (c + 1 < NCHUNK) {
            const char* src = (const char*)&g_esplit[c + 1][0];
            uint32_t dstb = sb + SM_B + ((c + 1) & 1) * B_BUF;
            for (int i = tid; i < CHUNK_BYTES / 16; i += THREADS) {
                int row = i >> 3, q = i & 7;
                CP_ASYNC16(dstb + row * ROWB + q * 16, src + row * 128 + q * 16);
            }
            CP_COMMIT();
        }

        float acc[4][8][4];
        #pragma unroll
        for (int mt = 0; mt < 4; mt++)
            #pragma unroll
            for (int nt = 0; nt < 8; nt++)
                #pragma unroll
                for (int r = 0; r < 4; r++) acc[mt][nt][r] = 0.0f;

        // 6 split-product pairs x 4 k-steps (R8 interleaved order)
        // with explicit B prefetch-by-one inside the nt loop.
        for (int p = 0; p < 6; p++) {
            int pa = (p < 3) ? p : ((p < 5) ? p - 3 : 0);
            int pb = (p < 3) ? 0 : ((p < 5) ? 1 : 2);
            uint32_t ab = aW + pa * A_BLK;
            uint32_t bb = bW + buf * B_BUF + pb * B_BLK;
            #pragma unroll
            for (int ks = 0; ks < 4; ks++) {
                uint32_t ko = ks * 32;           // 16 bf16 = 32 bytes
                uint32_t a[4][4];
                #pragma unroll
                for (int mt = 0; mt < 4; mt++) {
                    uint32_t base = ab + mt * 16 * ROWB + ko;
                    a[mt][0] = lds32(base);
                    a[mt][1] = lds32(base + 8 * ROWB);
                    a[mt][2] = lds32(base + 16);
                    a[mt][3] = lds32(base + 8 * ROWB + 16);
                }
                // prefetch nt=0 B fragments
                uint32_t b0c = lds32(bb + ko);
                uint32_t b1c = lds32(bb + ko + 16);
                #pragma unroll
                for (int nt = 0; nt < 8; nt++) {
                    uint32_t b0n = 0, b1n = 0;
                    if (nt < 7) {
                        uint32_t bbase = bb + (nt + 1) * 8 * ROWB + ko;
                        b0n = lds32(bbase);
                        b1n = lds32(bbase + 16);
                    }
                    #pragma unroll
                    for (int mt = 0; mt < 4; mt++)
                        mma16816(acc[mt][nt], a[mt], b0c, b1c);
                    b0c = b0n; b1c = b1n;
                }
            }
        }

        // Argmin on this chunk's distances
        #pragma unroll
        for (int nt = 0; nt < 8; nt++) {
            int cbase = c * KC + wn * 64 + nt * 8 + lr * 2;
            float2 en = *(const float2*)(se + cbase);
            #pragma unroll
            for (int mt = 0; mt < 4; mt++) {
                #pragma unroll
                for (int h = 0; h < 2; h++) {
                    int s = mt * 2 + h;
                    float m0 = fmaf(-2.0f, acc[mt][nt][2 * h],     en.x);
                    float m1 = fmaf(-2.0f, acc[mt][nt][2 * h + 1], en.y);
                    if (m0 < bestv[s] || (m0 == bestv[s] && cbase < besti[s]))
                        { bestv[s] = m0; besti[s] = cbase; }
                    if (m1 < bestv[s] || (m1 == bestv[s] && cbase + 1 < besti[s]))
                        { bestv[s] = m1; besti[s] = cbase + 1; }
                }
            }
        }

        CP_WAIT0();
        __syncthreads();
    }

    // Reduce across the 4 lanes (lr) sharing each token row
    #pragma unroll
    for (int s = 0; s < 8; s++) {
        #pragma unroll
        for (int off = 1; off <= 2; off <<= 1) {
            float ov = __shfl_xor_sync(0xffffffffu, bestv[s], off);
            int   oi = __shfl_xor_sync(0xffffffffu, besti[s], off);
            if (ov < bestv[s] || (ov == bestv[s] && oi < besti[s]))
                { bestv[s] = ov; besti[s] = oi; }
        }
    }
    if (lr == 0) {
        #pragma unroll
        for (int mt = 0; mt < 4; mt++)
            #pragma unroll
            for (int h = 0; h < 2; h++) {
                int t = wm * 64 + mt * 16 + lq + 8 * h;
                rv2[t * 2 + wn] = bestv[mt * 2 + h];
                ri2[t * 2 + wn] = besti[mt * 2 + h];
            }
    }
    __syncthreads();

    // Final per-token merge + outputs
    {
        float bv = rv2[tid * 2];
        int   bi = ri2[tid * 2];
        float v  = rv2[tid * 2 + 1];
        int   ix = ri2[tid * 2 + 1];
        if (v < bv || (v == bv && ix < bi)) { bv = v; bi = ix; }
        dout[IDX_OFF + b * LL + l0 + tid] = (float)bi;
        ii[tid] = bi;
        g_flags[bi] = 1;
        float sd = xns[tid] + bv;
        #pragma unroll
        for (int off = 16; off > 0; off >>= 1)
            sd += __shfl_down_sync(0xffffffffu, sd, off);
        if (lane == 0) ls[warp] = sd;
    }
    __syncthreads();
    if (tid == 0) {
        float s = 0.0f;
        #pragma unroll
        for (int w = 0; w < 8; w++) s += ls[w];
        g_partial[blockIdx.x] = s;
    }

    // Gather + transpose write (coalesced stores)
    for (int i = tid; i < DD * TM2; i += THREADS) {
        int d = i >> 8, t = i & 255;
        dout[((size_t)(b * DD + d)) * LL + l0 + t] = emb[(size_t)ii[t] * DD + d];
    }

    // ---- fused finalize: last CTA reduces loss + usage, resets state ----
    __threadfence();
    if (tid == 0) {
        int old = atomicAdd(&g_done, 1);
        amlast = (old == NBLK - 1) ? 1 : 0;
        cnt_s = 0;
    }
    __syncthreads();
    if (amlast) {
        __threadfence();
        float s = (tid < NBLK) ? g_partial[tid] : 0.0f;
        #pragma unroll
        for (int off = 16; off > 0; off >>= 1)
            s += __shfl_down_sync(0xffffffffu, s, off);
        if (lane == 0) ls[warp] = s;

        int f = 0;
        for (int i = tid; i < KK; i += THREADS) {
            f += g_flags[i];
            g_flags[i] = 0;
        }
        #pragma unroll
        for (int off = 16; off > 0; off >>= 1)
            f += __shfl_down_sync(0xffffffffu, f, off);
        if (lane == 0) atomicAdd(&cnt_s, f);
        __syncthreads();
        if (tid == 0) {
            float lsum = 0.0f;
            #pragma unroll
            for (int w = 0; w < 8; w++) lsum += ls[w];
            dout[LOSS_OFF]  = 11.0f * lsum / (float)(NN * DD);
            dout[USAGE_OFF] = (float)cnt_s;
            g_done = 0;
            __threadfence();
        }
    }
}

extern "C" void kernel_launch(void* const* d_in, const int* in_sizes, int n_in,
                              void* d_out, int out_size) {
    (void)n_in; (void)out_size;
    const float* x;
    const float* emb;
    if (in_sizes[0] == KK * DD) { emb = (const float*)d_in[0]; x = (const float*)d_in[1]; }
    else                        { x   = (const float*)d_in[0]; emb = (const float*)d_in[1]; }
    float* out = (float*)d_out;

    cudaFuncSetAttribute(vq_main, cudaFuncAttributeMaxDynamicSharedMemorySize,
                         SM_TOTAL);

    vq_prep<<<KPAD / 4, 256>>>(emb);
    vq_main<<<NBLK, THREADS, SM_TOTAL>>>(x, emb, out);
}

// round 13
// speedup vs baseline: 1.5461x; 1.0213x over previous
#include <cuda_runtime.h>
#include <cuda_bf16.h>
#include <cstdint>

#define BB   16
#define DD   64
#define LL   2048
#define KK   1000
#define KPAD 1024
#define NN   (BB * LL)             // 32768 tokens
#define TM2  256                   // tokens per CTA
#define KC   128                   // codes per chunk
#define NCHUNK 8
#define NBLK (NN / TM2)            // 128 CTAs
#define THREADS 256

#define OUT_ELEMS (BB * DD * LL)
#define LOSS_OFF  OUT_ELEMS
#define USAGE_OFF (OUT_ELEMS + 1)
#define IDX_OFF   (OUT_ELEMS + 2)

// SMEM layout (bytes). Token/code row stride = 72 bf16 = 144 B
#define ROWB     144
#define A_BLK    (TM2 * ROWB)          // 36864 per split block
#define SM_A     0                     // 3 blocks: 110592
#define B_BLK    (KC * ROWB)           // 18432 per split block
#define B_BUF    (3 * B_BLK)           // 55296 per buffer
#define SM_B     110592                // 2 buffers: 110592
#define SM_SE    221184                // float[1024] code norms
#define SM_XN    225280                // float[256] token norms
#define SM_RV    226304                // float[256][2]
#define SM_RI    228352                // int[256][2]
#define SM_II    230400                // int[256]
#define SM_LS    231424                // float[8]
#define SM_TOTAL 231488

#define CHUNK_BYTES (3 * KC * DD * 2)  // 49152 per chunk image

__device__ __align__(16) unsigned short g_esplit[NCHUNK][3 * KC * DD];
__device__ float g_enorm[KPAD];
__device__ float g_partial[NBLK];
__device__ int   g_flags[KK];
__device__ int   g_done;

// ---------------- helpers ----------------
__device__ __forceinline__ uint32_t smem_u32(const void* p) {
    uint32_t a;
    asm("{ .reg .u64 t; cvta.to.shared.u64 t, %1; cvt.u32.u64 %0, t; }"
        : "=r"(a) : "l"(p));
    return a;
}
__device__ __forceinline__ uint32_t lds32(uint32_t a) {
    uint32_t v;
    asm("ld.shared.b32 %0, [%1];" : "=r"(v) : "r"(a));
    return v;
}
__device__ __forceinline__ void sts32(uint32_t a, uint32_t v) {
    asm volatile("st.shared.b32 [%0], %1;" :: "r"(a), "r"(v) : "memory");
}
__device__ __forceinline__ void mma16816(float* c, const uint32_t* a,
                                         uint32_t b0, uint32_t b1) {
    asm volatile("mma.sync.aligned.m16n8k16.row.col.f32.bf16.bf16.f32 "
                 "{%0,%1,%2,%3}, {%4,%5,%6,%7}, {%8,%9}, {%0,%1,%2,%3};"
                 : "+f"(c[0]), "+f"(c[1]), "+f"(c[2]), "+f"(c[3])
                 : "r"(a[0]), "r"(a[1]), "r"(a[2]), "r"(a[3]),
                   "r"(b0), "r"(b1));
}
#define CP_ASYNC16(dst, src) \
    asm volatile("cp.async.cg.shared.global [%0], [%1], 16;" \
                 :: "r"(dst), "l"(src) : "memory")
#define CP_COMMIT() asm volatile("cp.async.commit_group;" ::: "memory")
#define CP_WAIT0()  asm volatile("cp.async.wait_group 0;" ::: "memory")

// ---- prep: 3-way bf16 split of codebook + fp32 norms ----
__global__ void __launch_bounds__(256, 4)
vq_prep(const float* __restrict__ emb) {
    __shared__ float hsum[8];
    int tid = threadIdx.x;
    int idx = blockIdx.x * 256 + tid;
    int k = idx >> 6, d = idx & 63;
    float e = (k < KK) ? emb[(size_t)k * DD + d] : 0.0f;

    float pn = e * e;
    #pragma unroll
    for (int off = 16; off > 0; off >>= 1)
        pn += __shfl_xor_sync(0xffffffffu, pn, off);
    if ((tid & 31) == 0) hsum[tid >> 5] = pn;

    __nv_bfloat16 b1 = __float2bfloat16(e);
    float r1 = e - __bfloat162float(b1);
    __nv_bfloat16 b2 = __float2bfloat16(r1);
    __nv_bfloat16 b3 = __float2bfloat16(r1 - __bfloat162float(b2));

    int ch = k >> 7, kc = k & 127;
    unsigned short* base = &g_esplit[ch][0];
    base[(0 * KC + kc) * DD + d] = __bfloat16_as_ushort(b1);
    base[(1 * KC + kc) * DD + d] = __bfloat16_as_ushort(b2);
    base[(2 * KC + kc) * DD + d] = __bfloat16_as_ushort(b3);

    __syncthreads();
    if (tid < 4) {
        int kk2 = blockIdx.x * 4 + tid;
        g_enorm[kk2] = (kk2 < KK) ? (hsum[2 * tid] + hsum[2 * tid + 1]) : 3.4e38f;
    }
}

// One pipelined (product,kstep) iteration: uses AC fragments for mma,
// loads AN fragments for iteration IT+1 interleaved into the nt loop,
// B fragments prefetched one nt ahead.
#define STEP(AC, AN, IT) do {                                              \
    const int p_ = (IT) >> 2;                                              \
    const uint32_t ko_ = (uint32_t)((IT) & 3) * 32u;                       \
    const int pb_ = (p_ < 3) ? 0 : ((p_ < 5) ? 1 : 2);                     \
    const uint32_t bb_ = bbase_buf + (uint32_t)pb_ * B_BLK;                \
    const int itn_ = (IT) + 1;                                             \
    const int pn_ = itn_ >> 2;                                             \
    const uint32_t kon_ = (uint32_t)(itn_ & 3) * 32u;                      \
    const int pan_ = (pn_ < 3) ? pn_ : ((pn_ < 5) ? pn_ - 3 : 0);          \
    const uint32_t abn_ = aW + (uint32_t)pan_ * A_BLK;                     \
    uint32_t b0c_ = lds32(bb_ + ko_);                                      \
    uint32_t b1c_ = lds32(bb_ + ko_ + 16);                                 \
    uint32_t b0n_ = 0, b1n_ = 0;                                           \
    _Pragma("unroll")                                                      \
    for (int nt_ = 0; nt_ < 8; nt_++) {                                    \
        if (nt_ < 7) {                                                     \
            uint32_t bnb_ = bb_ + (nt_ + 1) * 8 * ROWB + ko_;              \
            b0n_ = lds32(bnb_);                                            \
            b1n_ = lds32(bnb_ + 16);                                       \
        }                                                                  \
        if (nt_ < 4 && itn_ < 24) {                                        \
            uint32_t anb_ = abn_ + nt_ * 16 * ROWB + kon_;                 \
            AN[nt_][0] = lds32(anb_);                                      \
            AN[nt_][1] = lds32(anb_ + 8 * ROWB);                           \
            AN[nt_][2] = lds32(anb_ + 16);                                 \
            AN[nt_][3] = lds32(anb_ + 8 * ROWB + 16);                      \
        }                                                                  \
        mma16816(acc[0][nt_], AC[0], b0c_, b1c_);                          \
        mma16816(acc[1][nt_], AC[1], b0c_, b1c_);                          \
        mma16816(acc[2][nt_], AC[2], b0c_, b1c_);                          \
        mma16816(acc[3][nt_], AC[3], b0c_, b1c_);                          \
        b0c_ = b0n_; b1c_ = b1n_;                                          \
    }                                                                      \
} while (0)

// ---- main: HMMA split-GEMM + argmin + gather + loss + fused finalize ----
__global__ void __launch_bounds__(THREADS, 1)
vq_main(const float* __restrict__ x, const float* __restrict__ emb,
        float* __restrict__ dout) {
    extern __shared__ char smem[];
    const uint32_t sb = smem_u32(smem);
    float* se  = (float*)(smem + SM_SE);
    float* xns = (float*)(smem + SM_XN);
    float* rv2 = (float*)(smem + SM_RV);
    int*   ri2 = (int*)(smem + SM_RI);
    int*   ii  = (int*)(smem + SM_II);
    float* ls  = (float*)(smem + SM_LS);
    __shared__ int amlast;
    __shared__ int cnt_s;

    const int tid  = threadIdx.x;
    const int warp = tid >> 5;
    const int lane = tid & 31;
    const int wm   = warp & 3;     // m-slice (64 tokens)
    const int wn   = warp >> 2;    // n-slice (64 codes)
    const int lq   = lane >> 2;    // 0..7
    const int lr   = lane & 3;     // 0..3
    const int b    = blockIdx.x >> 3;
    const int l0   = (blockIdx.x & 7) * TM2;

    // Start B chunk-0 copy early (cp.async, overlaps A build)
    {
        const char* src = (const char*)&g_esplit[0][0];
        uint32_t dstb = sb + SM_B;
        for (int i = tid; i < CHUNK_BYTES / 16; i += THREADS) {
            int row = i >> 3, q = i & 7;
            CP_ASYNC16(dstb + row * ROWB + q * 16, src + row * 128 + q * 16);
        }
        CP_COMMIT();
    }

    // A build: thread owns token t = tid
    {
        const float* xp = x + (size_t)b * DD * LL + l0 + tid;
        float xn = 0.0f;
        #pragma unroll 4
        for (int d = 0; d < DD; d += 2) {
            float v0 = xp[(size_t)d * LL];
            float v1 = xp[(size_t)(d + 1) * LL];
            xn += v0 * v0 + v1 * v1;
            __nv_bfloat16 a1 = __float2bfloat16(v0);
            float r = v0 - __bfloat162float(a1);
            __nv_bfloat16 a2 = __float2bfloat16(r);
            __nv_bfloat16 a3 = __float2bfloat16(r - __bfloat162float(a2));
            __nv_bfloat16 c1 = __float2bfloat16(v1);
            float q = v1 - __bfloat162float(c1);
            __nv_bfloat16 c2 = __float2bfloat16(q);
            __nv_bfloat16 c3 = __float2bfloat16(q - __bfloat162float(c2));
            uint32_t base = sb + SM_A + tid * ROWB + d * 2;
            sts32(base,             (uint32_t)__bfloat16_as_ushort(a1) |
                                    ((uint32_t)__bfloat16_as_ushort(c1) << 16));
            sts32(base + A_BLK,     (uint32_t)__bfloat16_as_ushort(a2) |
                                    ((uint32_t)__bfloat16_as_ushort(c2) << 16));
            sts32(base + 2 * A_BLK, (uint32_t)__bfloat16_as_ushort(a3) |
                                    ((uint32_t)__bfloat16_as_ushort(c3) << 16));
        }
        xns[tid] = xn;
    }
    for (int i = tid; i < KPAD; i += THREADS) se[i] = g_enorm[i];

    CP_WAIT0();
    __syncthreads();

    float bestv[8];
    int   besti[8];
    #pragma unroll
    for (int s = 0; s < 8; s++) { bestv[s] = 3.0e38f; besti[s] = 0; }

    const uint32_t aW = sb + SM_A + wm * 64 * ROWB + lq * ROWB + lr * 4;
    const uint32_t bW = sb + SM_B + wn * 64 * ROWB + lq * ROWB + lr * 4;

    for (int c = 0; c < NCHUNK; c++) {
        const int buf = c & 1;
        if (c + 1 < NCHUNK) {
            const char* src = (const char*)&g_esplit[c + 1][0];
            uint32_t dstb = sb + SM_B + ((c + 1) & 1) * B_BUF;
            for (int i = tid; i < CHUNK_BYTES / 16; i += THREADS) {
                int row = i >> 3, q = i & 7;
                CP_ASYNC16(dstb + row * ROWB + q * 16, src + row * 128 + q * 16);
            }
            CP_COMMIT();
        }

        float acc[4][8][4];
        #pragma unroll
        for (int mt = 0; mt < 4; mt++)
            #pragma unroll
            for (int nt = 0; nt < 8; nt++)
                #pragma unroll
                for (int r = 0; r < 4; r++) acc[mt][nt][r] = 0.0f;

        const uint32_t bbase_buf = bW + buf * B_BUF;

        // Software-pipelined 24 (product,kstep) iterations:
        // A fragments double-buffered across iterations.
        uint32_t acur[4][4], anx[4][4];
        #pragma unroll
        for (int mt = 0; mt < 4; mt++) {
            uint32_t base = aW + mt * 16 * ROWB;   // it=0: pa=0, ko=0
            acur[mt][0] = lds32(base);
            acur[mt][1] = lds32(base + 8 * ROWB);
            acur[mt][2] = lds32(base + 16);
            acur[mt][3] = lds32(base + 8 * ROWB + 16);
        }
        #pragma unroll 2
        for (int it = 0; it < 24; it += 2) {
            STEP(acur, anx, it);
            STEP(anx, acur, it + 1);
        }

        // Argmin on this chunk's distances
        #pragma unroll
        for (int nt = 0; nt < 8; nt++) {
            int cbase = c * KC + wn * 64 + nt * 8 + lr * 2;
            float2 en = *(const float2*)(se + cbase);
            #pragma unroll
            for (int mt = 0; mt < 4; mt++) {
                #pragma unroll
                for (int h = 0; h < 2; h++) {
                    int s = mt * 2 + h;
                    float m0 = fmaf(-2.0f, acc[mt][nt][2 * h],     en.x);
                    float m1 = fmaf(-2.0f, acc[mt][nt][2 * h + 1], en.y);
                    if (m0 < bestv[s] || (m0 == bestv[s] && cbase < besti[s]))
                        { bestv[s] = m0; besti[s] = cbase; }
                    if (m1 < bestv[s] || (m1 == bestv[s] && cbase + 1 < besti[s]))
                        { bestv[s] = m1; besti[s] = cbase + 1; }
                }
            }
        }

        CP_WAIT0();
        __syncthreads();
    }

    // Reduce across the 4 lanes (lr) sharing each token row
    #pragma unroll
    for (int s = 0; s < 8; s++) {
        #pragma unroll
        for (int off = 1; off <= 2; off <<= 1) {
            float ov = __shfl_xor_sync(0xffffffffu, bestv[s], off);
            int   oi = __shfl_xor_sync(0xffffffffu, besti[s], off);
            if (ov < bestv[s] || (ov == bestv[s] && oi < besti[s]))
                { bestv[s] = ov; besti[s] = oi; }
        }
    }
    if (lr == 0) {
        #pragma unroll
        for (int mt = 0; mt < 4; mt++)
            #pragma unroll
            for (int h = 0; h < 2; h++) {
                int t = wm * 64 + mt * 16 + lq + 8 * h;
                rv2[t * 2 + wn] = bestv[mt * 2 + h];
                ri2[t * 2 + wn] = besti[mt * 2 + h];
            }
    }
    __syncthreads();

    // Final per-token merge + outputs
    {
        float bv = rv2[tid * 2];
        int   bi = ri2[tid * 2];
        float v  = rv2[tid * 2 + 1];
        int   ix = ri2[tid * 2 + 1];
        if (v < bv || (v == bv && ix < bi)) { bv = v; bi = ix; }
        dout[IDX_OFF + b * LL + l0 + tid] = (float)bi;
        ii[tid] = bi;
        g_flags[bi] = 1;
        float sd = xns[tid] + bv;
        #pragma unroll
        for (int off = 16; off > 0; off >>= 1)
            sd += __shfl_down_sync(0xffffffffu, sd, off);
        if (lane == 0) ls[warp] = sd;
    }
    __syncthreads();
    if (tid == 0) {
        float s = 0.0f;
        #pragma unroll
        for (int w = 0; w < 8; w++) s += ls[w];
        g_partial[blockIdx.x] = s;
    }

    // Gather + transpose write (coalesced stores)
    for (int i = tid; i < DD * TM2; i += THREADS) {
        int d = i >> 8, t = i & 255;
        dout[((size_t)(b * DD + d)) * LL + l0 + t] = emb[(size_t)ii[t] * DD + d];
    }

    // ---- fused finalize: last CTA reduces loss + usage, resets state ----
    __threadfence();
    if (tid == 0) {
        int old = atomicAdd(&g_done, 1);
        amlast = (old == NBLK - 1) ? 1 : 0;
        cnt_s = 0;
    }
    __syncthreads();
    if (amlast) {
        __threadfence();
        float s = (tid < NBLK) ? g_partial[tid] : 0.0f;
        #pragma unroll
        for (int off = 16; off > 0; off >>= 1)
            s += __shfl_down_sync(0xffffffffu, s, off);
        if (lane == 0) ls[warp] = s;

        int f = 0;
        for (int i = tid; i < KK; i += THREADS) {
            f += g_flags[i];
            g_flags[i] = 0;
        }
        #pragma unroll
        for (int off = 16; off > 0; off >>= 1)
            f += __shfl_down_sync(0xffffffffu, f, off);
        if (lane == 0) atomicAdd(&cnt_s, f);
        __syncthreads();
        if (tid == 0) {
            float lsum = 0.0f;
            #pragma unroll
            for (int w = 0; w < 8; w++) lsum += ls[w];
            dout[LOSS_OFF]  = 11.0f * lsum / (float)(NN * DD);
            dout[USAGE_OFF] = (float)cnt_s;
            g_done = 0;
            __threadfence();
        }
    }
}

extern "C" void kernel_launch(void* const* d_in, const int* in_sizes, int n_in,
                              void* d_out, int out_size) {
    (void)n_in; (void)out_size;
    const float* x;
    const float* emb;
    if (in_sizes[0] == KK * DD) { emb = (const float*)d_in[0]; x = (const float*)d_in[1]; }
    else                        { x   = (const float*)d_in[0]; emb = (const float*)d_in[1]; }
    float* out = (float*)d_out;

    cudaFuncSetAttribute(vq_main, cudaFuncAttributeMaxDynamicSharedMemorySize,
                         SM_TOTAL);

    vq_prep<<<KPAD / 4, 256>>>(emb);
    vq_main<<<NBLK, THREADS, SM_TOTAL>>>(x, emb, out);
}